// round 6
// baseline (speedup 1.0000x reference)
#include <cuda_runtime.h>
#include <math.h>

#define BS 8
#define D 256
#define L 1024
#define H 8
#define DK 32
#define EPSV 1e-8f

typedef unsigned long long u64;

// ---- f32x2 packed-math helpers (sm_100+ FFMA2) ------------------------------
__device__ __forceinline__ u64 f2dup(float x) {
    u64 r; asm("mov.b64 %0, {%1, %1};" : "=l"(r) : "f"(x)); return r;
}
__device__ __forceinline__ u64 f2pack(float lo, float hi) {
    u64 r; asm("mov.b64 %0, {%1, %2};" : "=l"(r) : "f"(lo), "f"(hi)); return r;
}
__device__ __forceinline__ void fma2(u64& d, u64 a, u64 b) {
    asm("fma.rn.f32x2 %0, %1, %2, %0;" : "+l"(d) : "l"(a), "l"(b));
}
__device__ __forceinline__ float2 f2unpack(u64 v) {
    float2 f; asm("mov.b64 {%0, %1}, %2;" : "=f"(f.x), "=f"(f.y) : "l"(v)); return f;
}

// Scratch (device globals -> no allocations, graph-capture safe)
__device__ float g_q[BS * D * L];   // [b*H+h][c][l], pre-masked
__device__ float g_k[BS * D * L];   // [b*H+h][c][l], pre-masked
__device__ float g_v[BS * D * L];   // [b*H+h][c][l], pre-masked
__device__ float g_val[BS * L * D]; // [b][l][c]  (attention output, pre-Wp)

// ---------------------------------------------------------------------------
// Kernel 1: grouped 1x1 conv projection. 2 adjacent l's per thread so the
// 256 weight LDS per thread amortize over 2x the FMA work (fma-bound now).
// ---------------------------------------------------------------------------
__global__ __launch_bounds__(256) void proj_kernel(
    const float* __restrict__ q, const float* __restrict__ k,
    const float* __restrict__ v, const float* __restrict__ mask,
    const float* __restrict__ Wq, const float* __restrict__ Wk,
    const float* __restrict__ Wv)
{
    __shared__ float wt[DK * DK];   // wt[j][i] = W[i][j]
    const int h = blockIdx.y;
    const int z = blockIdx.z;
    const int b = z / 3;
    const int which = z - b * 3;
    const int t = threadIdx.x;

    const float* __restrict__ X = (which == 0) ? q : (which == 1) ? k : v;
    const float* __restrict__ W = (which == 0) ? Wq : (which == 1) ? Wk : Wv;
    float* __restrict__ O = (which == 0) ? g_q : (which == 1) ? g_k : g_v;

    for (int idx = t; idx < DK * DK; idx += 256) {
        int j = idx >> 5, i = idx & 31;
        wt[j * DK + i] = W[h * DK * DK + i * DK + j];
    }
    __syncthreads();

    const int l0 = blockIdx.x * 512 + t * 2;
    const float mv0 = mask[b * L + l0];
    const float mv1 = mask[b * L + l0 + 1];
    const int xbase = (b * D + h * DK) * L + l0;
    const int obase = (b * H + h) * DK * L + l0;

    u64 acc[2][16];
    #pragma unroll
    for (int p = 0; p < 2; p++)
        #pragma unroll
        for (int i = 0; i < 16; i++) acc[p][i] = 0ull;

    #pragma unroll
    for (int j = 0; j < DK; j++) {
        float2 xv = *(const float2*)&X[xbase + j * L];
        u64 x0 = f2dup(xv.x);
        u64 x1 = f2dup(xv.y);
        #pragma unroll
        for (int q4 = 0; q4 < 8; q4++) {
            float4 w4 = *(const float4*)&wt[j * DK + q4 * 4];
            u64 wp0 = f2pack(w4.x, w4.y);
            u64 wp1 = f2pack(w4.z, w4.w);
            fma2(acc[0][q4 * 2 + 0], x0, wp0);
            fma2(acc[0][q4 * 2 + 1], x0, wp1);
            fma2(acc[1][q4 * 2 + 0], x1, wp0);
            fma2(acc[1][q4 * 2 + 1], x1, wp1);
        }
    }

    #pragma unroll
    for (int ip = 0; ip < 16; ip++) {
        float2 r0 = f2unpack(acc[0][ip]);   // l0:   i = 2ip, 2ip+1
        float2 r1 = f2unpack(acc[1][ip]);   // l0+1: i = 2ip, 2ip+1
        *(float2*)&O[obase + (2 * ip + 0) * L] = make_float2(r0.x * mv0, r1.x * mv1);
        *(float2*)&O[obase + (2 * ip + 1) * L] = make_float2(r0.y * mv0, r1.y * mv1);
    }
}

// ---------------------------------------------------------------------------
// Kernel 2: fused attention per (b,h). P never touches smem: thread tile is
// 2 rows x 8 n-cols; each thread accumulates partial O[2][32] over its own
// n-subset; final 3-step lane butterfly (xor 1,2,4) completes the n-sum.
// V tile is XOR-swizzled so PV loads are bank-conflict-free.
// K/V/mask for the next tile are prefetched into registers (latency hiding).
// ---------------------------------------------------------------------------
#define MT 64
#define NT 64

__global__ __launch_bounds__(256, 1) void attn_kernel(const float* __restrict__ mask)
{
    __shared__ __align__(16) float Qs[DK * MT];   // [c][m]
    __shared__ __align__(16) float Ks[DK * NT];   // [c][n]
    __shared__ __align__(16) float Vs[NT * 32];   // [n][c] xor-swizzled chunks

    const int bh = blockIdx.y;
    const int b = bh / H;
    const int row0 = blockIdx.x * MT;

    const float* __restrict__ qp = g_q + bh * DK * L;
    const float* __restrict__ kp = g_k + bh * DK * L;
    const float* __restrict__ vp = g_v + bh * DK * L;
    const float* __restrict__ mp = mask + b * L;

    const int t = threadIdx.x;
    const int rg = t >> 3;        // 0..31 -> rows
    const int cg = t & 7;         // 0..7  -> n-columns
    const int r0 = rg * 2;
    const int c0 = cg * 8;

    // fill coordinates for K/V tiles (8 elems/thread)
    int fc[8], fn[8];
    #pragma unroll
    for (int i = 0; i < 8; i++) {
        int idx = i * 256 + t;
        fc[i] = idx >> 6;
        fn[i] = idx & 63;
    }

    // load Q tile [c][m] (ordered by the in-loop syncthreads before use)
    for (int i = t; i < DK * MT; i += 256) {
        int c = i >> 6, m = i & 63;
        Qs[c * MT + m] = qp[c * L + row0 + m];
    }

    // prefetch tile 0
    float kb[8], vb[8];
    #pragma unroll
    for (int i = 0; i < 8; i++) {
        kb[i] = kp[fc[i] * L + fn[i]];
        vb[i] = vp[fc[i] * L + fn[i]];
    }
    float4 mn0 = *(const float4*)&mp[c0];
    float4 mn1 = *(const float4*)&mp[c0 + 4];

    u64 o2[2][16];                 // [row][c-pair]  (32 head-dims)
    #pragma unroll
    for (int r = 0; r < 2; r++)
        #pragma unroll
        for (int i = 0; i < 16; i++) o2[r][i] = 0ull;
    float ps0 = 0.f, ps1 = 0.f;    // partial row sums over own n's

    for (int col0 = 0; col0 < L; col0 += NT) {
        __syncthreads();   // smem free (prev compute done; Q fill on iter 0)

        #pragma unroll
        for (int i = 0; i < 8; i++) {
            int cc = fc[i], nn = fn[i];
            Ks[cc * NT + nn] = kb[i];
            int js = (cc >> 2) ^ (nn & 7) ^ (nn >> 3);
            Vs[nn * 32 + js * 4 + (cc & 3)] = vb[i];
        }
        __syncthreads();

        const float cm[8] = {mn0.x, mn0.y, mn0.z, mn0.w, mn1.x, mn1.y, mn1.z, mn1.w};

        // prefetch next tile while computing this one
        int nxt = col0 + NT;
        if (nxt < L) {
            #pragma unroll
            for (int i = 0; i < 8; i++) {
                kb[i] = kp[fc[i] * L + nxt + fn[i]];
                vb[i] = vp[fc[i] * L + nxt + fn[i]];
            }
            mn0 = *(const float4*)&mp[nxt + c0];
            mn1 = *(const float4*)&mp[nxt + c0 + 4];
        }

        // ---- S = Q^T K : 2 rows x 8 cols, FFMA2 over n-pairs ----
        u64 acc[2][4];
        #pragma unroll
        for (int r = 0; r < 2; r++)
            #pragma unroll
            for (int i = 0; i < 4; i++) acc[r][i] = 0ull;

        #pragma unroll
        for (int c = 0; c < DK; c++) {
            float2 qv = *(const float2*)&Qs[c * MT + r0];
            float4 k0 = *(const float4*)&Ks[c * NT + c0];
            float4 k1 = *(const float4*)&Ks[c * NT + c0 + 4];
            u64 k01 = f2pack(k0.x, k0.y);
            u64 k23 = f2pack(k0.z, k0.w);
            u64 k45 = f2pack(k1.x, k1.y);
            u64 k67 = f2pack(k1.z, k1.w);
            u64 q0 = f2dup(qv.x);
            u64 q1 = f2dup(qv.y);
            fma2(acc[0][0], q0, k01); fma2(acc[0][1], q0, k23);
            fma2(acc[0][2], q0, k45); fma2(acc[0][3], q0, k67);
            fma2(acc[1][0], q1, k01); fma2(acc[1][1], q1, k23);
            fma2(acc[1][2], q1, k45); fma2(acc[1][3], q1, k67);
        }

        // ---- P = mask * exp(S) (stays in registers) ----
        float P0[8], P1[8];
        #pragma unroll
        for (int i = 0; i < 4; i++) {
            float2 a0 = f2unpack(acc[0][i]);
            float2 a1 = f2unpack(acc[1][i]);
            P0[2 * i + 0] = cm[2 * i + 0] * __expf(a0.x);
            P0[2 * i + 1] = cm[2 * i + 1] * __expf(a0.y);
            P1[2 * i + 0] = cm[2 * i + 0] * __expf(a1.x);
            P1[2 * i + 1] = cm[2 * i + 1] * __expf(a1.y);
        }
        #pragma unroll
        for (int i = 0; i < 8; i++) { ps0 += P0[i]; ps1 += P1[i]; }

        // ---- O_partial += P[own n] * V[own n][:] ----
        #pragma unroll
        for (int n = 0; n < 8; n++) {
            u64 pd0 = f2dup(P0[n]);
            u64 pd1 = f2dup(P1[n]);
            const float* vrow = &Vs[(c0 + n) * 32];
            #pragma unroll
            for (int j = 0; j < 8; j++) {
                int js = j ^ n ^ cg;   // logical chunk j at swizzled slot
                float4 vv = *(const float4*)&vrow[js * 4];
                u64 v01 = f2pack(vv.x, vv.y);
                u64 v23 = f2pack(vv.z, vv.w);
                fma2(o2[0][2 * j + 0], pd0, v01);
                fma2(o2[0][2 * j + 1], pd0, v23);
                fma2(o2[1][2 * j + 0], pd1, v01);
                fma2(o2[1][2 * j + 1], pd1, v23);
            }
        }
    }

    // ---- reduce row sums over the 8 n-groups (lanes cg=0..7) ----
    #pragma unroll
    for (int d = 1; d < 8; d <<= 1) {
        ps0 += __shfl_xor_sync(0xFFFFFFFFu, ps0, d);
        ps1 += __shfl_xor_sync(0xFFFFFFFFu, ps1, d);
    }
    const float inv0 = 1.0f / (ps0 + EPSV);
    const float inv1 = 1.0f / (ps1 + EPSV);

    // ---- butterfly-reduce O over the 8 n-groups, halving c-range each step ----
    float of[2][32];
    #pragma unroll
    for (int r = 0; r < 2; r++)
        #pragma unroll
        for (int i = 0; i < 16; i++) {
            float2 p = f2unpack(o2[r][i]);
            of[r][2 * i] = p.x; of[r][2 * i + 1] = p.y;
        }

    int coff = 0;
    // step d=1: keep 16
    #pragma unroll
    for (int r = 0; r < 2; r++)
        #pragma unroll
        for (int i = 0; i < 16; i++) {
            float send = (cg & 1) ? of[r][i] : of[r][i + 16];
            float recv = __shfl_xor_sync(0xFFFFFFFFu, send, 1);
            of[r][i] = ((cg & 1) ? of[r][i + 16] : of[r][i]) + recv;
        }
    coff += (cg & 1) * 16;
    // step d=2: keep 8
    #pragma unroll
    for (int r = 0; r < 2; r++)
        #pragma unroll
        for (int i = 0; i < 8; i++) {
            float send = (cg & 2) ? of[r][i] : of[r][i + 8];
            float recv = __shfl_xor_sync(0xFFFFFFFFu, send, 2);
            of[r][i] = ((cg & 2) ? of[r][i + 8] : of[r][i]) + recv;
        }
    coff += ((cg >> 1) & 1) * 8;
    // step d=4: keep 4
    #pragma unroll
    for (int r = 0; r < 2; r++)
        #pragma unroll
        for (int i = 0; i < 4; i++) {
            float send = (cg & 4) ? of[r][i] : of[r][i + 4];
            float recv = __shfl_xor_sync(0xFFFFFFFFu, send, 4);
            of[r][i] = ((cg & 4) ? of[r][i + 4] : of[r][i]) + recv;
        }
    coff += ((cg >> 2) & 1) * 4;

    // ---- store: g_val[b][row][h*32 + coff .. +3] ----
    const int h = bh - b * H;
    {
        int row = row0 + r0;
        float4 res0 = make_float4(of[0][0] * inv0, of[0][1] * inv0,
                                  of[0][2] * inv0, of[0][3] * inv0);
        float4 res1 = make_float4(of[1][0] * inv1, of[1][1] * inv1,
                                  of[1][2] * inv1, of[1][3] * inv1);
        *(float4*)&g_val[(b * L + row)     * D + h * DK + coff] = res0;
        *(float4*)&g_val[(b * L + row + 1) * D + h * DK + coff] = res1;
    }
}

// ---------------------------------------------------------------------------
// Kernel 3: out = mask * (Wp @ val + bp), output layout (B, L, D)
// Tile 64(l) x 64(i), K-chunks of 32. FFMA2 over l-row-pairs.
// ---------------------------------------------------------------------------
#define OK_LD 68

__global__ __launch_bounds__(256) void out_kernel(
    const float* __restrict__ Wp, const float* __restrict__ bp,
    const float* __restrict__ mask, float* __restrict__ out)
{
    __shared__ __align__(16) float As[32 * OK_LD];   // [j][l]
    __shared__ __align__(16) float Bsm[32 * OK_LD];  // [j][i]

    const int b = blockIdx.z;
    const int i0 = blockIdx.y * 64;
    const int l0 = blockIdx.x * 64;
    const int t = threadIdx.x;
    const int rg = t >> 4, cg = t & 15;
    const int lr = rg * 4, ic = cg * 4;

    const float* __restrict__ val = g_val + b * L * D;

    u64 acc2[2][4];   // [l-pair][i]
    #pragma unroll
    for (int p = 0; p < 2; p++)
        #pragma unroll
        for (int i = 0; i < 4; i++) acc2[p][i] = 0ull;

    for (int j0 = 0; j0 < D; j0 += 32) {
        __syncthreads();
        for (int idx = t; idx < 64 * 32; idx += 256) {
            int ll = idx >> 5, j = idx & 31;
            As[j * OK_LD + ll] = val[(l0 + ll) * D + j0 + j];
        }
        for (int idx = t; idx < 64 * 32; idx += 256) {
            int ii = idx >> 5, j = idx & 31;
            Bsm[j * OK_LD + ii] = Wp[(i0 + ii) * D + j0 + j];
        }
        __syncthreads();

        #pragma unroll
        for (int kk = 0; kk < 32; kk++) {
            float4 av = *(const float4*)&As[kk * OK_LD + lr];
            float4 bv = *(const float4*)&Bsm[kk * OK_LD + ic];
            u64 a01 = f2pack(av.x, av.y);
            u64 a23 = f2pack(av.z, av.w);
            u64 b0 = f2dup(bv.x), b1 = f2dup(bv.y), b2 = f2dup(bv.z), b3 = f2dup(bv.w);
            fma2(acc2[0][0], a01, b0); fma2(acc2[1][0], a23, b0);
            fma2(acc2[0][1], a01, b1); fma2(acc2[1][1], a23, b1);
            fma2(acc2[0][2], a01, b2); fma2(acc2[1][2], a23, b2);
            fma2(acc2[0][3], a01, b3); fma2(acc2[1][3], a23, b3);
        }
    }

    const float bv0 = bp[i0 + ic + 0];
    const float bv1 = bp[i0 + ic + 1];
    const float bv2 = bp[i0 + ic + 2];
    const float bv3 = bp[i0 + ic + 3];

    float2 c0r = f2unpack(acc2[0][0]), c1r = f2unpack(acc2[0][1]);
    float2 c2r = f2unpack(acc2[0][2]), c3r = f2unpack(acc2[0][3]);
    float2 d0r = f2unpack(acc2[1][0]), d1r = f2unpack(acc2[1][1]);
    float2 d2r = f2unpack(acc2[1][2]), d3r = f2unpack(acc2[1][3]);

    float rows[4][4] = {
        {c0r.x, c1r.x, c2r.x, c3r.x},
        {c0r.y, c1r.y, c2r.y, c3r.y},
        {d0r.x, d1r.x, d2r.x, d3r.x},
        {d0r.y, d1r.y, d2r.y, d3r.y},
    };

    #pragma unroll
    for (int p = 0; p < 4; p++) {
        float mv = mask[b * L + l0 + lr + p];
        float4 r;
        r.x = (rows[p][0] + bv0) * mv;
        r.y = (rows[p][1] + bv1) * mv;
        r.z = (rows[p][2] + bv2) * mv;
        r.w = (rows[p][3] + bv3) * mv;
        *(float4*)&out[((size_t)(b * L + l0 + lr + p)) * D + i0 + ic] = r;
    }
}

// ---------------------------------------------------------------------------
extern "C" void kernel_launch(void* const* d_in, const int* in_sizes, int n_in,
                              void* d_out, int out_size)
{
    const float* q    = (const float*)d_in[0];
    const float* k    = (const float*)d_in[1];
    const float* v    = (const float*)d_in[2];
    const float* mask = (const float*)d_in[3];
    const float* Wq   = (const float*)d_in[4];
    const float* Wk   = (const float*)d_in[5];
    const float* Wv   = (const float*)d_in[6];
    const float* Wp   = (const float*)d_in[7];
    const float* bp   = (const float*)d_in[8];
    float* out = (float*)d_out;

    proj_kernel<<<dim3(L / 512, H, BS * 3), 256>>>(q, k, v, mask, Wq, Wk, Wv);
    attn_kernel<<<dim3(L / MT, BS * H), 256>>>(mask);
    out_kernel<<<dim3(L / 64, D / 64, BS), 256>>>(Wp, bp, mask, out);
}

// round 7
// speedup vs baseline: 1.4437x; 1.4437x over previous
#include <cuda_runtime.h>
#include <math.h>

#define BS 8
#define D 256
#define L 1024
#define H 8
#define DK 32
#define EPSV 1e-8f

typedef unsigned long long u64;

// ---- f32x2 packed-math helpers (sm_100+ FFMA2) ------------------------------
__device__ __forceinline__ u64 f2dup(float x) {
    u64 r; asm("mov.b64 %0, {%1, %1};" : "=l"(r) : "f"(x)); return r;
}
__device__ __forceinline__ u64 f2pack(float lo, float hi) {
    u64 r; asm("mov.b64 %0, {%1, %2};" : "=l"(r) : "f"(lo), "f"(hi)); return r;
}
__device__ __forceinline__ void fma2(u64& d, u64 a, u64 b) {
    asm("fma.rn.f32x2 %0, %1, %2, %0;" : "+l"(d) : "l"(a), "l"(b));
}
__device__ __forceinline__ float2 f2unpack(u64 v) {
    float2 f; asm("mov.b64 {%0, %1}, %2;" : "=f"(f.x), "=f"(f.y) : "l"(v)); return f;
}

// Scratch (device globals -> no allocations, graph-capture safe)
__device__ float g_q[BS * D * L];   // [b*H+h][c][l], pre-masked
__device__ float g_k[BS * D * L];   // [b*H+h][c][l], pre-masked
__device__ float g_v[BS * D * L];   // [b*H+h][c][l], pre-masked
__device__ float g_val[BS * L * D]; // [b][l][c]  (attention output, pre-Wp)

// ---------------------------------------------------------------------------
// Kernel 1: grouped 1x1 conv projection. 2 adjacent l's per thread.
// ---------------------------------------------------------------------------
__global__ __launch_bounds__(256) void proj_kernel(
    const float* __restrict__ q, const float* __restrict__ k,
    const float* __restrict__ v, const float* __restrict__ mask,
    const float* __restrict__ Wq, const float* __restrict__ Wk,
    const float* __restrict__ Wv)
{
    __shared__ float wt[DK * DK];   // wt[j][i] = W[i][j]
    const int h = blockIdx.y;
    const int z = blockIdx.z;
    const int b = z / 3;
    const int which = z - b * 3;
    const int t = threadIdx.x;

    const float* __restrict__ X = (which == 0) ? q : (which == 1) ? k : v;
    const float* __restrict__ W = (which == 0) ? Wq : (which == 1) ? Wk : Wv;
    float* __restrict__ O = (which == 0) ? g_q : (which == 1) ? g_k : g_v;

    for (int idx = t; idx < DK * DK; idx += 256) {
        int j = idx >> 5, i = idx & 31;
        wt[j * DK + i] = W[h * DK * DK + i * DK + j];
    }
    __syncthreads();

    const int l0 = blockIdx.x * 512 + t * 2;
    const float mv0 = mask[b * L + l0];
    const float mv1 = mask[b * L + l0 + 1];
    const int xbase = (b * D + h * DK) * L + l0;
    const int obase = (b * H + h) * DK * L + l0;

    u64 acc[2][16];
    #pragma unroll
    for (int p = 0; p < 2; p++)
        #pragma unroll
        for (int i = 0; i < 16; i++) acc[p][i] = 0ull;

    #pragma unroll
    for (int j = 0; j < DK; j++) {
        float2 xv = *(const float2*)&X[xbase + j * L];
        u64 x0 = f2dup(xv.x);
        u64 x1 = f2dup(xv.y);
        #pragma unroll
        for (int q4 = 0; q4 < 8; q4++) {
            float4 w4 = *(const float4*)&wt[j * DK + q4 * 4];
            u64 wp0 = f2pack(w4.x, w4.y);
            u64 wp1 = f2pack(w4.z, w4.w);
            fma2(acc[0][q4 * 2 + 0], x0, wp0);
            fma2(acc[0][q4 * 2 + 1], x0, wp1);
            fma2(acc[1][q4 * 2 + 0], x1, wp0);
            fma2(acc[1][q4 * 2 + 1], x1, wp1);
        }
    }

    #pragma unroll
    for (int ip = 0; ip < 16; ip++) {
        float2 r0 = f2unpack(acc[0][ip]);
        float2 r1 = f2unpack(acc[1][ip]);
        *(float2*)&O[obase + (2 * ip + 0) * L] = make_float2(r0.x * mv0, r1.x * mv1);
        *(float2*)&O[obase + (2 * ip + 1) * L] = make_float2(r0.y * mv0, r1.y * mv1);
    }
}

// ---------------------------------------------------------------------------
// Kernel 2: fused attention per (b,h) — R4 structure + register prefetch of
// the next K/V tile so global-load latency overlaps compute.
// ---------------------------------------------------------------------------
#define MT 64
#define NT 64
#define PS_LD 68   // P row pitch
#define VS_LD 36   // V row pitch

__global__ __launch_bounds__(256) void attn_kernel(const float* __restrict__ mask)
{
    __shared__ __align__(16) float Qs[DK * MT];      // [c][m]
    __shared__ __align__(16) float Ks[DK * NT];      // [c][n]
    __shared__ __align__(16) float Vs[NT * VS_LD];   // [n][c] padded
    __shared__ __align__(16) float Ps[MT * PS_LD];   // [r][n] padded
    __shared__ float mk[NT];
    __shared__ float lsum[MT];

    const int bh = blockIdx.y;
    const int b = bh / H;
    const int row0 = blockIdx.x * MT;

    const float* __restrict__ qp = g_q + bh * DK * L;
    const float* __restrict__ kp = g_k + bh * DK * L;
    const float* __restrict__ vp = g_v + bh * DK * L;
    const float* __restrict__ mp = mask + b * L;

    const int t = threadIdx.x;
    // QK / softmax mapping: 16 row-groups x 16 col-groups, tile 4x4
    const int rg = t >> 4;
    const int cg = t & 15;
    const int r0 = rg * 4;
    const int c0 = cg * 4;
    // PV mapping: 32 row-groups (2 rows) x 8 col-groups (4 cols)
    const int r0b = (t >> 3) * 2;
    const int c0b = (t & 7) * 4;

    // fill coordinates for K/V tiles (8 elems/thread)
    int fc[8], fn[8];
    #pragma unroll
    for (int i = 0; i < 8; i++) {
        int idx = i * 256 + t;
        fc[i] = idx >> 6;
        fn[i] = idx & 63;
    }

    // load Q tile [c][m]
    for (int i = t; i < DK * MT; i += 256) {
        int c = i >> 6, m = i & 63;
        Qs[c * MT + m] = qp[c * L + row0 + m];
    }

    // prefetch tile 0 into registers
    float kb[8], vb[8];
    #pragma unroll
    for (int i = 0; i < 8; i++) {
        kb[i] = kp[fc[i] * L + fn[i]];
        vb[i] = vp[fc[i] * L + fn[i]];
    }
    float mreg = (t < NT) ? mp[t] : 0.f;

    u64 o2[2][2];       // [row within pair][col-pair]
    o2[0][0] = 0ull; o2[0][1] = 0ull; o2[1][0] = 0ull; o2[1][1] = 0ull;
    float ps[4] = {0.f, 0.f, 0.f, 0.f};   // partial row sums (QK mapping)

    for (int col0 = 0; col0 < L; col0 += NT) {
        __syncthreads();  // prior-iter Ps/Vs reads done (and Q fill, iter 0)

        #pragma unroll
        for (int i = 0; i < 8; i++) {
            Ks[fc[i] * NT + fn[i]] = kb[i];
            Vs[fn[i] * VS_LD + fc[i]] = vb[i];   // transposed store
        }
        if (t < NT) mk[t] = mreg;
        __syncthreads();

        // prefetch next tile while computing this one
        int nxt = col0 + NT;
        if (nxt < L) {
            #pragma unroll
            for (int i = 0; i < 8; i++) {
                kb[i] = kp[fc[i] * L + nxt + fn[i]];
                vb[i] = vp[fc[i] * L + nxt + fn[i]];
            }
            mreg = (t < NT) ? mp[nxt + t] : 0.f;
        }

        // ---- S = Q^T K, FFMA2 with natural Q row-pairs, dup'd K ----
        u64 acc2[2][4];
        #pragma unroll
        for (int p = 0; p < 2; p++)
            #pragma unroll
            for (int i = 0; i < 4; i++) acc2[p][i] = 0ull;

        #pragma unroll
        for (int c = 0; c < DK; c++) {
            float4 qv = *(const float4*)&Qs[c * MT + r0];
            float4 kv = *(const float4*)&Ks[c * NT + c0];
            u64 q01 = f2pack(qv.x, qv.y);
            u64 q23 = f2pack(qv.z, qv.w);
            u64 kd0 = f2dup(kv.x), kd1 = f2dup(kv.y), kd2 = f2dup(kv.z), kd3 = f2dup(kv.w);
            fma2(acc2[0][0], q01, kd0); fma2(acc2[1][0], q23, kd0);
            fma2(acc2[0][1], q01, kd1); fma2(acc2[1][1], q23, kd1);
            fma2(acc2[0][2], q01, kd2); fma2(acc2[1][2], q23, kd2);
            fma2(acc2[0][3], q01, kd3); fma2(acc2[1][3], q23, kd3);
        }

        const float m0 = mk[c0 + 0], m1 = mk[c0 + 1], m2 = mk[c0 + 2], m3 = mk[c0 + 3];

        // ---- p = mask * exp(s); accumulate row sums; stage P ----
        #pragma unroll
        for (int half = 0; half < 2; half++) {
            float2 a0 = f2unpack(acc2[half][0]);
            float2 a1 = f2unpack(acc2[half][1]);
            float2 a2 = f2unpack(acc2[half][2]);
            float2 a3 = f2unpack(acc2[half][3]);

            float p0 = m0 * __expf(a0.x), p1 = m1 * __expf(a1.x);
            float p2 = m2 * __expf(a2.x), p3 = m3 * __expf(a3.x);
            ps[2 * half + 0] += (p0 + p1) + (p2 + p3);
            *(float4*)&Ps[(r0 + 2 * half + 0) * PS_LD + c0] = make_float4(p0, p1, p2, p3);

            float q0 = m0 * __expf(a0.y), q1 = m1 * __expf(a1.y);
            float q2 = m2 * __expf(a2.y), q3 = m3 * __expf(a3.y);
            ps[2 * half + 1] += (q0 + q1) + (q2 + q3);
            *(float4*)&Ps[(r0 + 2 * half + 1) * PS_LD + c0] = make_float4(q0, q1, q2, q3);
        }
        __syncthreads();

        // ---- O += P * V^T : FFMA2, natural V col-pairs, dup'd P ----
        #pragma unroll 4
        for (int n0 = 0; n0 < NT; n0 += 4) {
            float4 pa = *(const float4*)&Ps[(r0b + 0) * PS_LD + n0];
            float4 pb = *(const float4*)&Ps[(r0b + 1) * PS_LD + n0];
            const float pav[4] = {pa.x, pa.y, pa.z, pa.w};
            const float pbv[4] = {pb.x, pb.y, pb.z, pb.w};
            #pragma unroll
            for (int j = 0; j < 4; j++) {
                float4 vv = *(const float4*)&Vs[(n0 + j) * VS_LD + c0b];
                u64 v01 = f2pack(vv.x, vv.y);
                u64 v23 = f2pack(vv.z, vv.w);
                u64 pd0 = f2dup(pav[j]);
                u64 pd1 = f2dup(pbv[j]);
                fma2(o2[0][0], pd0, v01); fma2(o2[0][1], pd0, v23);
                fma2(o2[1][0], pd1, v01); fma2(o2[1][1], pd1, v23);
            }
        }
    }

    // ---- row-sum reduction across the 16 col-groups (width-16 shuffles) ----
    #pragma unroll
    for (int r = 0; r < 4; r++) {
        float s = ps[r];
        #pragma unroll
        for (int mm = 1; mm < 16; mm <<= 1)
            s += __shfl_xor_sync(0xFFFFFFFFu, s, mm, 16);
        if (cg == 0) lsum[r0 + r] = s;
    }
    __syncthreads();

    // ---- epilogue: normalize, store to g_val[b][l][h*DK + c] ----
    const int h = bh - b * H;
    #pragma unroll
    for (int rr = 0; rr < 2; rr++) {
        float inv = 1.0f / (lsum[r0b + rr] + EPSV);
        float2 lo = f2unpack(o2[rr][0]);
        float2 hi = f2unpack(o2[rr][1]);
        int row = row0 + r0b + rr;
        float4 res = make_float4(lo.x * inv, lo.y * inv, hi.x * inv, hi.y * inv);
        *(float4*)&g_val[(b * L + row) * D + h * DK + c0b] = res;
    }
}

// ---------------------------------------------------------------------------
// Kernel 3: out = mask * (Wp @ val + bp), output layout (B, L, D)
// Tile 64(l) x 64(i), K-chunks of 32, register-prefetch pipelined.
// ---------------------------------------------------------------------------
#define OK_LD 68

__global__ __launch_bounds__(256) void out_kernel(
    const float* __restrict__ Wp, const float* __restrict__ bp,
    const float* __restrict__ mask, float* __restrict__ out)
{
    __shared__ __align__(16) float As[32 * OK_LD];   // [j][l]
    __shared__ __align__(16) float Bsm[32 * OK_LD];  // [j][i]

    const int b = blockIdx.z;
    const int i0 = blockIdx.y * 64;
    const int l0 = blockIdx.x * 64;
    const int t = threadIdx.x;
    const int rg = t >> 4, cg = t & 15;
    const int lr = rg * 4, ic = cg * 4;

    const float* __restrict__ val = g_val + b * L * D;

    // fill coords: 8 elements each for As and Bsm
    int fl[8], fj[8];
    #pragma unroll
    for (int i = 0; i < 8; i++) {
        int idx = i * 256 + t;
        fl[i] = idx >> 5;
        fj[i] = idx & 31;
    }

    // prefetch chunk 0
    float ab[8], bb[8];
    #pragma unroll
    for (int i = 0; i < 8; i++) {
        ab[i] = val[(l0 + fl[i]) * D + fj[i]];
        bb[i] = Wp[(i0 + fl[i]) * D + fj[i]];
    }

    u64 acc2[2][4];   // [l-pair][i]
    #pragma unroll
    for (int p = 0; p < 2; p++)
        #pragma unroll
        for (int i = 0; i < 4; i++) acc2[p][i] = 0ull;

    for (int j0 = 0; j0 < D; j0 += 32) {
        __syncthreads();
        #pragma unroll
        for (int i = 0; i < 8; i++) {
            As[fj[i] * OK_LD + fl[i]] = ab[i];
            Bsm[fj[i] * OK_LD + fl[i]] = bb[i];
        }
        __syncthreads();

        int jn = j0 + 32;
        if (jn < D) {
            #pragma unroll
            for (int i = 0; i < 8; i++) {
                ab[i] = val[(l0 + fl[i]) * D + jn + fj[i]];
                bb[i] = Wp[(i0 + fl[i]) * D + jn + fj[i]];
            }
        }

        #pragma unroll
        for (int kk = 0; kk < 32; kk++) {
            float4 av = *(const float4*)&As[kk * OK_LD + lr];
            float4 bv = *(const float4*)&Bsm[kk * OK_LD + ic];
            u64 a01 = f2pack(av.x, av.y);
            u64 a23 = f2pack(av.z, av.w);
            u64 b0 = f2dup(bv.x), b1 = f2dup(bv.y), b2 = f2dup(bv.z), b3 = f2dup(bv.w);
            fma2(acc2[0][0], a01, b0); fma2(acc2[1][0], a23, b0);
            fma2(acc2[0][1], a01, b1); fma2(acc2[1][1], a23, b1);
            fma2(acc2[0][2], a01, b2); fma2(acc2[1][2], a23, b2);
            fma2(acc2[0][3], a01, b3); fma2(acc2[1][3], a23, b3);
        }
    }

    const float bv0 = bp[i0 + ic + 0];
    const float bv1 = bp[i0 + ic + 1];
    const float bv2 = bp[i0 + ic + 2];
    const float bv3 = bp[i0 + ic + 3];

    float2 c0r = f2unpack(acc2[0][0]), c1r = f2unpack(acc2[0][1]);
    float2 c2r = f2unpack(acc2[0][2]), c3r = f2unpack(acc2[0][3]);
    float2 d0r = f2unpack(acc2[1][0]), d1r = f2unpack(acc2[1][1]);
    float2 d2r = f2unpack(acc2[1][2]), d3r = f2unpack(acc2[1][3]);

    float rows[4][4] = {
        {c0r.x, c1r.x, c2r.x, c3r.x},
        {c0r.y, c1r.y, c2r.y, c3r.y},
        {d0r.x, d1r.x, d2r.x, d3r.x},
        {d0r.y, d1r.y, d2r.y, d3r.y},
    };

    #pragma unroll
    for (int p = 0; p < 4; p++) {
        float mv = mask[b * L + l0 + lr + p];
        float4 r;
        r.x = (rows[p][0] + bv0) * mv;
        r.y = (rows[p][1] + bv1) * mv;
        r.z = (rows[p][2] + bv2) * mv;
        r.w = (rows[p][3] + bv3) * mv;
        *(float4*)&out[((size_t)(b * L + l0 + lr + p)) * D + i0 + ic] = r;
    }
}

// ---------------------------------------------------------------------------
extern "C" void kernel_launch(void* const* d_in, const int* in_sizes, int n_in,
                              void* d_out, int out_size)
{
    const float* q    = (const float*)d_in[0];
    const float* k    = (const float*)d_in[1];
    const float* v    = (const float*)d_in[2];
    const float* mask = (const float*)d_in[3];
    const float* Wq   = (const float*)d_in[4];
    const float* Wk   = (const float*)d_in[5];
    const float* Wv   = (const float*)d_in[6];
    const float* Wp   = (const float*)d_in[7];
    const float* bp   = (const float*)d_in[8];
    float* out = (float*)d_out;

    proj_kernel<<<dim3(L / 512, H, BS * 3), 256>>>(q, k, v, mask, Wq, Wk, Wv);
    attn_kernel<<<dim3(L / MT, BS * H), 256>>>(mask);
    out_kernel<<<dim3(L / 64, D / 64, BS), 256>>>(Wp, bp, mask, out);
}

// round 8
// speedup vs baseline: 1.6254x; 1.1259x over previous
#include <cuda_runtime.h>
#include <math.h>

#define BS 8
#define D 256
#define L 1024
#define H 8
#define DK 32
#define EPSV 1e-8f

typedef unsigned long long u64;

// ---- f32x2 packed-math helpers (sm_100+ FFMA2) ------------------------------
__device__ __forceinline__ u64 f2dup(float x) {
    u64 r; asm("mov.b64 %0, {%1, %1};" : "=l"(r) : "f"(x)); return r;
}
__device__ __forceinline__ u64 f2pack(float lo, float hi) {
    u64 r; asm("mov.b64 %0, {%1, %2};" : "=l"(r) : "f"(lo), "f"(hi)); return r;
}
__device__ __forceinline__ void fma2(u64& d, u64 a, u64 b) {
    asm("fma.rn.f32x2 %0, %1, %2, %0;" : "+l"(d) : "l"(a), "l"(b));
}
__device__ __forceinline__ float2 f2unpack(u64 v) {
    float2 f; asm("mov.b64 {%0, %1}, %2;" : "=f"(f.x), "=f"(f.y) : "l"(v)); return f;
}

// Scratch (device globals -> no allocations, graph-capture safe)
__device__ float g_q[BS * D * L];   // [b*H+h][c][l], pre-masked
__device__ float g_k[BS * D * L];   // [b*H+h][c][l], pre-masked
__device__ float g_v[BS * D * L];   // [b*H+h][c][l], pre-masked
__device__ float g_val[BS * L * D]; // [b][l][c]  (attention output, pre-Wp)

// ---------------------------------------------------------------------------
// Kernel 1: grouped 1x1 conv projection. 2 adjacent l's per thread.
// ---------------------------------------------------------------------------
__global__ __launch_bounds__(256) void proj_kernel(
    const float* __restrict__ q, const float* __restrict__ k,
    const float* __restrict__ v, const float* __restrict__ mask,
    const float* __restrict__ Wq, const float* __restrict__ Wk,
    const float* __restrict__ Wv)
{
    __shared__ float wt[DK * DK];   // wt[j][i] = W[i][j]
    const int h = blockIdx.y;
    const int z = blockIdx.z;
    const int b = z / 3;
    const int which = z - b * 3;
    const int t = threadIdx.x;

    const float* __restrict__ X = (which == 0) ? q : (which == 1) ? k : v;
    const float* __restrict__ W = (which == 0) ? Wq : (which == 1) ? Wk : Wv;
    float* __restrict__ O = (which == 0) ? g_q : (which == 1) ? g_k : g_v;

    for (int idx = t; idx < DK * DK; idx += 256) {
        int j = idx >> 5, i = idx & 31;
        wt[j * DK + i] = W[h * DK * DK + i * DK + j];
    }
    __syncthreads();

    const int l0 = blockIdx.x * 512 + t * 2;
    const float mv0 = mask[b * L + l0];
    const float mv1 = mask[b * L + l0 + 1];
    const int xbase = (b * D + h * DK) * L + l0;
    const int obase = (b * H + h) * DK * L + l0;

    u64 acc[2][16];
    #pragma unroll
    for (int p = 0; p < 2; p++)
        #pragma unroll
        for (int i = 0; i < 16; i++) acc[p][i] = 0ull;

    #pragma unroll
    for (int j = 0; j < DK; j++) {
        float2 xv = *(const float2*)&X[xbase + j * L];
        u64 x0 = f2dup(xv.x);
        u64 x1 = f2dup(xv.y);
        #pragma unroll
        for (int q4 = 0; q4 < 8; q4++) {
            float4 w4 = *(const float4*)&wt[j * DK + q4 * 4];
            u64 wp0 = f2pack(w4.x, w4.y);
            u64 wp1 = f2pack(w4.z, w4.w);
            fma2(acc[0][q4 * 2 + 0], x0, wp0);
            fma2(acc[0][q4 * 2 + 1], x0, wp1);
            fma2(acc[1][q4 * 2 + 0], x1, wp0);
            fma2(acc[1][q4 * 2 + 1], x1, wp1);
        }
    }

    #pragma unroll
    for (int ip = 0; ip < 16; ip++) {
        float2 r0 = f2unpack(acc[0][ip]);
        float2 r1 = f2unpack(acc[1][ip]);
        *(float2*)&O[obase + (2 * ip + 0) * L] = make_float2(r0.x * mv0, r1.x * mv1);
        *(float2*)&O[obase + (2 * ip + 1) * L] = make_float2(r0.y * mv0, r1.y * mv1);
    }
}

// ---------------------------------------------------------------------------
// Kernel 2: fused attention per (b,h). MT=128, bigger register tiles to cut
// LDS-per-FLOP ~1.6x (the measured bottleneck).
//   QK: thread tile 8 rows x 4 cols (3 LDS.128 -> 16 fma2 per c-step)
//   PV: thread tile 4 rows x 8 dims, k-split by 2 across thread halves,
//       combined once at the end through smem scratch.
// ---------------------------------------------------------------------------
#define MT 128
#define NT 64
#define PS_LD 68
#define VS_LD 36
// smem float offsets
#define SME_QS 0
#define SME_KS (DK * MT)                    // 4096
#define SME_VS (SME_KS + DK * NT)           // 6144
#define SME_PS (SME_VS + NT * VS_LD)        // 8448
#define SME_MK (SME_PS + MT * PS_LD)        // 17152
#define SME_LS (SME_MK + NT)                // 17216
#define SMEM_FLOATS (SME_LS + MT)           // 17344
#define SMEM_BYTES (SMEM_FLOATS * 4)        // 69376

__global__ __launch_bounds__(256) void attn_kernel(const float* __restrict__ mask)
{
    extern __shared__ __align__(16) float sm[];
    float* Qs = sm + SME_QS;      // [c][m]
    float* Ks = sm + SME_KS;      // [c][n]
    float* Vs = sm + SME_VS;      // [n][c] padded
    float* Ps = sm + SME_PS;      // [r][n] padded  (reused as combine scratch)
    float* mk = sm + SME_MK;
    float* lsum = sm + SME_LS;

    const int bh = blockIdx.y;
    const int b = bh / H;
    const int row0 = blockIdx.x * MT;

    const float* __restrict__ qp = g_q + bh * DK * L;
    const float* __restrict__ kp = g_k + bh * DK * L;
    const float* __restrict__ vp = g_v + bh * DK * L;
    const float* __restrict__ mp = mask + b * L;

    const int t = threadIdx.x;
    // QK / softmax mapping: 16 row-groups (8 rows) x 16 col-groups (4 cols)
    const int rg = t >> 4;
    const int cg = t & 15;
    const int r0 = rg * 8;
    const int c0 = cg * 4;
    // PV mapping: k-split by 2; within half: 32 row-groups (4 rows) x 4 c-groups (8 dims)
    const int tk = t >> 7;                  // 0/1 -> n-half
    const int r0p = ((t & 127) >> 2) * 4;
    const int c0p = (t & 3) * 8;
    const int nbase = tk * 32;

    // load Q tile [c][m]
    for (int i = t; i < DK * MT; i += 256) {
        int c = i >> 7, m = i & 127;
        Qs[c * MT + m] = qp[c * L + row0 + m];
    }

    // prefetch tile 0 into registers
    float kb[8], vb[8];
    #pragma unroll
    for (int i = 0; i < 8; i++) {
        int idx = i * 256 + t;
        kb[i] = kp[(idx >> 6) * L + (idx & 63)];
        vb[i] = vp[(idx >> 6) * L + (idx & 63)];
    }
    float mreg = (t < NT) ? mp[t] : 0.f;

    u64 o2[16];                 // O acc: [4 rows][4 c-pairs]
    #pragma unroll
    for (int i = 0; i < 16; i++) o2[i] = 0ull;
    float ps[8] = {0.f, 0.f, 0.f, 0.f, 0.f, 0.f, 0.f, 0.f};  // row-sum partials

    for (int col0 = 0; col0 < L; col0 += NT) {
        __syncthreads();  // prior-iter Ps/Vs/Ks reads done (and Q fill, iter 0)

        #pragma unroll
        for (int i = 0; i < 8; i++) {
            int idx = i * 256 + t;
            int cc = idx >> 6, nn = idx & 63;
            Ks[cc * NT + nn] = kb[i];
            Vs[nn * VS_LD + cc] = vb[i];   // transposed store
        }
        if (t < NT) mk[t] = mreg;
        __syncthreads();

        // prefetch next tile while computing this one
        int nxt = col0 + NT;
        if (nxt < L) {
            #pragma unroll
            for (int i = 0; i < 8; i++) {
                int idx = i * 256 + t;
                kb[i] = kp[(idx >> 6) * L + nxt + (idx & 63)];
                vb[i] = vp[(idx >> 6) * L + nxt + (idx & 63)];
            }
            mreg = (t < NT) ? mp[nxt + t] : 0.f;
        }

        // ---- S = Q^T K : 8 rows x 4 cols via FFMA2 (row-pairs x dup'd K) ----
        u64 acc[4][4];   // [row-pair][col]
        #pragma unroll
        for (int p = 0; p < 4; p++)
            #pragma unroll
            for (int i = 0; i < 4; i++) acc[p][i] = 0ull;

        #pragma unroll
        for (int c = 0; c < DK; c++) {
            float4 qa = *(const float4*)&Qs[c * MT + r0];
            float4 qb = *(const float4*)&Qs[c * MT + r0 + 4];
            float4 kv = *(const float4*)&Ks[c * NT + c0];
            u64 q01 = f2pack(qa.x, qa.y);
            u64 q23 = f2pack(qa.z, qa.w);
            u64 q45 = f2pack(qb.x, qb.y);
            u64 q67 = f2pack(qb.z, qb.w);
            u64 kd0 = f2dup(kv.x), kd1 = f2dup(kv.y), kd2 = f2dup(kv.z), kd3 = f2dup(kv.w);
            fma2(acc[0][0], q01, kd0); fma2(acc[0][1], q01, kd1);
            fma2(acc[0][2], q01, kd2); fma2(acc[0][3], q01, kd3);
            fma2(acc[1][0], q23, kd0); fma2(acc[1][1], q23, kd1);
            fma2(acc[1][2], q23, kd2); fma2(acc[1][3], q23, kd3);
            fma2(acc[2][0], q45, kd0); fma2(acc[2][1], q45, kd1);
            fma2(acc[2][2], q45, kd2); fma2(acc[2][3], q45, kd3);
            fma2(acc[3][0], q67, kd0); fma2(acc[3][1], q67, kd1);
            fma2(acc[3][2], q67, kd2); fma2(acc[3][3], q67, kd3);
        }

        // ---- p = mask * exp(s); accumulate row partials; stage P ----
        const float4 mkv = *(const float4*)&mk[c0];
        #pragma unroll
        for (int rp = 0; rp < 4; rp++) {
            float2 a0 = f2unpack(acc[rp][0]);
            float2 a1 = f2unpack(acc[rp][1]);
            float2 a2 = f2unpack(acc[rp][2]);
            float2 a3 = f2unpack(acc[rp][3]);

            float p0 = mkv.x * __expf(a0.x), p1 = mkv.y * __expf(a1.x);
            float p2 = mkv.z * __expf(a2.x), p3 = mkv.w * __expf(a3.x);
            ps[2 * rp + 0] += (p0 + p1) + (p2 + p3);
            *(float4*)&Ps[(r0 + 2 * rp + 0) * PS_LD + c0] = make_float4(p0, p1, p2, p3);

            float q0 = mkv.x * __expf(a0.y), q1 = mkv.y * __expf(a1.y);
            float q2 = mkv.z * __expf(a2.y), q3 = mkv.w * __expf(a3.y);
            ps[2 * rp + 1] += (q0 + q1) + (q2 + q3);
            *(float4*)&Ps[(r0 + 2 * rp + 1) * PS_LD + c0] = make_float4(q0, q1, q2, q3);
        }
        __syncthreads();

        // ---- O += P * V^T over own n-half : 4 rows x 8 dims ----
        #pragma unroll 4
        for (int n0 = 0; n0 < 32; n0 += 4) {
            const int na = nbase + n0;
            float4 pr0 = *(const float4*)&Ps[(r0p + 0) * PS_LD + na];
            float4 pr1 = *(const float4*)&Ps[(r0p + 1) * PS_LD + na];
            float4 pr2 = *(const float4*)&Ps[(r0p + 2) * PS_LD + na];
            float4 pr3 = *(const float4*)&Ps[(r0p + 3) * PS_LD + na];
            const float pv0[4] = {pr0.x, pr0.y, pr0.z, pr0.w};
            const float pv1[4] = {pr1.x, pr1.y, pr1.z, pr1.w};
            const float pv2[4] = {pr2.x, pr2.y, pr2.z, pr2.w};
            const float pv3[4] = {pr3.x, pr3.y, pr3.z, pr3.w};
            #pragma unroll
            for (int j = 0; j < 4; j++) {
                float4 va = *(const float4*)&Vs[(na + j) * VS_LD + c0p];
                float4 vbb = *(const float4*)&Vs[(na + j) * VS_LD + c0p + 4];
                u64 v01 = f2pack(va.x, va.y);
                u64 v23 = f2pack(va.z, va.w);
                u64 v45 = f2pack(vbb.x, vbb.y);
                u64 v67 = f2pack(vbb.z, vbb.w);
                u64 pd0 = f2dup(pv0[j]);
                u64 pd1 = f2dup(pv1[j]);
                u64 pd2 = f2dup(pv2[j]);
                u64 pd3 = f2dup(pv3[j]);
                fma2(o2[0],  pd0, v01); fma2(o2[1],  pd0, v23);
                fma2(o2[2],  pd0, v45); fma2(o2[3],  pd0, v67);
                fma2(o2[4],  pd1, v01); fma2(o2[5],  pd1, v23);
                fma2(o2[6],  pd1, v45); fma2(o2[7],  pd1, v67);
                fma2(o2[8],  pd2, v01); fma2(o2[9],  pd2, v23);
                fma2(o2[10], pd2, v45); fma2(o2[11], pd2, v67);
                fma2(o2[12], pd3, v01); fma2(o2[13], pd3, v23);
                fma2(o2[14], pd3, v45); fma2(o2[15], pd3, v67);
            }
        }
    }

    __syncthreads();   // all PV reads of Ps done -> safe to reuse as scratch

    // ---- half tk=1 parks its partial O in scratch (reuse Ps) ----
    float of[4][8];
    #pragma unroll
    for (int i = 0; i < 4; i++)
        #pragma unroll
        for (int jc = 0; jc < 4; jc++) {
            float2 p = f2unpack(o2[i * 4 + jc]);
            of[i][2 * jc] = p.x; of[i][2 * jc + 1] = p.y;
        }
    if (tk == 1) {
        float* s = Ps + (t & 127) * 32;
        #pragma unroll
        for (int i = 0; i < 4; i++) {
            *(float4*)&s[i * 8]     = make_float4(of[i][0], of[i][1], of[i][2], of[i][3]);
            *(float4*)&s[i * 8 + 4] = make_float4(of[i][4], of[i][5], of[i][6], of[i][7]);
        }
    }

    // ---- row-sum reduction across the 16 col-groups (width-16 shuffles) ----
    #pragma unroll
    for (int r = 0; r < 8; r++) {
        float s = ps[r];
        #pragma unroll
        for (int mm = 1; mm < 16; mm <<= 1)
            s += __shfl_xor_sync(0xFFFFFFFFu, s, mm, 16);
        if (cg == 0) lsum[r0 + r] = s;
    }
    __syncthreads();

    // ---- half tk=0 combines, normalizes, stores ----
    if (tk == 0) {
        const int h = bh - b * H;
        const float* s = Ps + t * 32;
        #pragma unroll
        for (int i = 0; i < 4; i++) {
            float4 sa = *(const float4*)&s[i * 8];
            float4 sb = *(const float4*)&s[i * 8 + 4];
            float inv = 1.0f / (lsum[r0p + i] + EPSV);
            int row = row0 + r0p + i;
            float4 ra = make_float4((of[i][0] + sa.x) * inv, (of[i][1] + sa.y) * inv,
                                    (of[i][2] + sa.z) * inv, (of[i][3] + sa.w) * inv);
            float4 rb = make_float4((of[i][4] + sb.x) * inv, (of[i][5] + sb.y) * inv,
                                    (of[i][6] + sb.z) * inv, (of[i][7] + sb.w) * inv);
            *(float4*)&g_val[(b * L + row) * D + h * DK + c0p] = ra;
            *(float4*)&g_val[(b * L + row) * D + h * DK + c0p + 4] = rb;
        }
    }
}

// ---------------------------------------------------------------------------
// Kernel 3: out = mask * (Wp @ val + bp), output layout (B, L, D)
// ---------------------------------------------------------------------------
#define OK_LD 68

__global__ __launch_bounds__(256) void out_kernel(
    const float* __restrict__ Wp, const float* __restrict__ bp,
    const float* __restrict__ mask, float* __restrict__ out)
{
    __shared__ __align__(16) float As[32 * OK_LD];   // [j][l]
    __shared__ __align__(16) float Bsm[32 * OK_LD];  // [j][i]

    const int b = blockIdx.z;
    const int i0 = blockIdx.y * 64;
    const int l0 = blockIdx.x * 64;
    const int t = threadIdx.x;
    const int rg = t >> 4, cg = t & 15;
    const int lr = rg * 4, ic = cg * 4;

    const float* __restrict__ val = g_val + b * L * D;

    int fl[8], fj[8];
    #pragma unroll
    for (int i = 0; i < 8; i++) {
        int idx = i * 256 + t;
        fl[i] = idx >> 5;
        fj[i] = idx & 31;
    }

    float ab[8], bb[8];
    #pragma unroll
    for (int i = 0; i < 8; i++) {
        ab[i] = val[(l0 + fl[i]) * D + fj[i]];
        bb[i] = Wp[(i0 + fl[i]) * D + fj[i]];
    }

    u64 acc2[2][4];   // [l-pair][i]
    #pragma unroll
    for (int p = 0; p < 2; p++)
        #pragma unroll
        for (int i = 0; i < 4; i++) acc2[p][i] = 0ull;

    for (int j0 = 0; j0 < D; j0 += 32) {
        __syncthreads();
        #pragma unroll
        for (int i = 0; i < 8; i++) {
            As[fj[i] * OK_LD + fl[i]] = ab[i];
            Bsm[fj[i] * OK_LD + fl[i]] = bb[i];
        }
        __syncthreads();

        int jn = j0 + 32;
        if (jn < D) {
            #pragma unroll
            for (int i = 0; i < 8; i++) {
                ab[i] = val[(l0 + fl[i]) * D + jn + fj[i]];
                bb[i] = Wp[(i0 + fl[i]) * D + jn + fj[i]];
            }
        }

        #pragma unroll
        for (int kk = 0; kk < 32; kk++) {
            float4 av = *(const float4*)&As[kk * OK_LD + lr];
            float4 bv = *(const float4*)&Bsm[kk * OK_LD + ic];
            u64 a01 = f2pack(av.x, av.y);
            u64 a23 = f2pack(av.z, av.w);
            u64 b0 = f2dup(bv.x), b1 = f2dup(bv.y), b2 = f2dup(bv.z), b3 = f2dup(bv.w);
            fma2(acc2[0][0], a01, b0); fma2(acc2[1][0], a23, b0);
            fma2(acc2[0][1], a01, b1); fma2(acc2[1][1], a23, b1);
            fma2(acc2[0][2], a01, b2); fma2(acc2[1][2], a23, b2);
            fma2(acc2[0][3], a01, b3); fma2(acc2[1][3], a23, b3);
        }
    }

    const float bv0 = bp[i0 + ic + 0];
    const float bv1 = bp[i0 + ic + 1];
    const float bv2 = bp[i0 + ic + 2];
    const float bv3 = bp[i0 + ic + 3];

    float2 c0r = f2unpack(acc2[0][0]), c1r = f2unpack(acc2[0][1]);
    float2 c2r = f2unpack(acc2[0][2]), c3r = f2unpack(acc2[0][3]);
    float2 d0r = f2unpack(acc2[1][0]), d1r = f2unpack(acc2[1][1]);
    float2 d2r = f2unpack(acc2[1][2]), d3r = f2unpack(acc2[1][3]);

    float rows[4][4] = {
        {c0r.x, c1r.x, c2r.x, c3r.x},
        {c0r.y, c1r.y, c2r.y, c3r.y},
        {d0r.x, d1r.x, d2r.x, d3r.x},
        {d0r.y, d1r.y, d2r.y, d3r.y},
    };

    #pragma unroll
    for (int p = 0; p < 4; p++) {
        float mv = mask[b * L + l0 + lr + p];
        float4 r;
        r.x = (rows[p][0] + bv0) * mv;
        r.y = (rows[p][1] + bv1) * mv;
        r.z = (rows[p][2] + bv2) * mv;
        r.w = (rows[p][3] + bv3) * mv;
        *(float4*)&out[((size_t)(b * L + l0 + lr + p)) * D + i0 + ic] = r;
    }
}

// ---------------------------------------------------------------------------
extern "C" void kernel_launch(void* const* d_in, const int* in_sizes, int n_in,
                              void* d_out, int out_size)
{
    const float* q    = (const float*)d_in[0];
    const float* k    = (const float*)d_in[1];
    const float* v    = (const float*)d_in[2];
    const float* mask = (const float*)d_in[3];
    const float* Wq   = (const float*)d_in[4];
    const float* Wk   = (const float*)d_in[5];
    const float* Wv   = (const float*)d_in[6];
    const float* Wp   = (const float*)d_in[7];
    const float* bp   = (const float*)d_in[8];
    float* out = (float*)d_out;

    cudaFuncSetAttribute(attn_kernel, cudaFuncAttributeMaxDynamicSharedMemorySize, SMEM_BYTES);

    proj_kernel<<<dim3(L / 512, H, BS * 3), 256>>>(q, k, v, mask, Wq, Wk, Wv);
    attn_kernel<<<dim3(L / MT, BS * H), 256, SMEM_BYTES>>>(mask);
    out_kernel<<<dim3(L / 64, D / 64, BS), 256>>>(Wp, bp, mask, out);
}

// round 9
// speedup vs baseline: 3.0342x; 1.8667x over previous
#include <cuda_runtime.h>
#include <cuda_bf16.h>
#include <math.h>

#define BS 8
#define D 256
#define L 1024
#define H 8
#define DK 32
#define EPSV 1e-8f

typedef unsigned int u32;
typedef unsigned long long u64;

// ---- f32x2 packed-math helpers (kept for proj/out kernels) ------------------
__device__ __forceinline__ u64 f2dup(float x) {
    u64 r; asm("mov.b64 %0, {%1, %1};" : "=l"(r) : "f"(x)); return r;
}
__device__ __forceinline__ u64 f2pack(float lo, float hi) {
    u64 r; asm("mov.b64 %0, {%1, %2};" : "=l"(r) : "f"(lo), "f"(hi)); return r;
}
__device__ __forceinline__ void fma2(u64& d, u64 a, u64 b) {
    asm("fma.rn.f32x2 %0, %1, %2, %0;" : "+l"(d) : "l"(a), "l"(b));
}
__device__ __forceinline__ float2 f2unpack(u64 v) {
    float2 f; asm("mov.b64 {%0, %1}, %2;" : "=f"(f.x), "=f"(f.y) : "l"(v)); return f;
}

// ---- tensor-core helpers ----------------------------------------------------
__device__ __forceinline__ u32 smaddr(const void* p) {
    return (u32)__cvta_generic_to_shared(p);
}
__device__ __forceinline__ void ldsm4(u32& r0, u32& r1, u32& r2, u32& r3, u32 a) {
    asm volatile("ldmatrix.sync.aligned.m8n8.x4.shared.b16 {%0,%1,%2,%3}, [%4];"
        : "=r"(r0), "=r"(r1), "=r"(r2), "=r"(r3) : "r"(a));
}
__device__ __forceinline__ void ldsm4t(u32& r0, u32& r1, u32& r2, u32& r3, u32 a) {
    asm volatile("ldmatrix.sync.aligned.m8n8.x4.trans.shared.b16 {%0,%1,%2,%3}, [%4];"
        : "=r"(r0), "=r"(r1), "=r"(r2), "=r"(r3) : "r"(a));
}
__device__ __forceinline__ void mma16816(float* c, const u32* a, u32 b0, u32 b1) {
    asm volatile("mma.sync.aligned.m16n8k16.row.col.f32.bf16.bf16.f32 "
        "{%0,%1,%2,%3}, {%4,%5,%6,%7}, {%8,%9}, {%0,%1,%2,%3};"
        : "+f"(c[0]), "+f"(c[1]), "+f"(c[2]), "+f"(c[3])
        : "r"(a[0]), "r"(a[1]), "r"(a[2]), "r"(a[3]), "r"(b0), "r"(b1));
}
// pack two floats to bf16x2: hi arg -> upper half, lo arg -> lower half
__device__ __forceinline__ u32 cvtbf2(float hi, float lo) {
    u32 d; asm("cvt.rn.bf16x2.f32 %0, %1, %2;" : "=r"(d) : "f"(hi), "f"(lo)); return d;
}
// split x into (hi bf16 in low16, lo bf16 in high16)
__device__ __forceinline__ u32 packsplit(float x) {
    __nv_bfloat16 hb = __float2bfloat16(x);
    u32 hbits = (u32)__bfloat16_as_ushort(hb);
    float hf = __uint_as_float(hbits << 16);
    __nv_bfloat16 lb = __float2bfloat16(x - hf);
    return ((u32)__bfloat16_as_ushort(lb) << 16) | hbits;
}

// Scratch (device globals)
__device__ u32 g_qp[BS * D * L];    // [bh][c][l] packed (bf16 hi | lo<<16), pre-masked
__device__ u32 g_kp[BS * D * L];
__device__ u32 g_vp[BS * D * L];
__device__ float g_val[BS * L * D]; // [b][l][c]

// ---------------------------------------------------------------------------
// Kernel 1: grouped 1x1 conv projection -> packed bf16 hi/lo planes.
// ---------------------------------------------------------------------------
__global__ __launch_bounds__(256) void proj_kernel(
    const float* __restrict__ q, const float* __restrict__ k,
    const float* __restrict__ v, const float* __restrict__ mask,
    const float* __restrict__ Wq, const float* __restrict__ Wk,
    const float* __restrict__ Wv)
{
    __shared__ float wt[DK * DK];   // wt[j][i] = W[i][j]
    const int h = blockIdx.y;
    const int z = blockIdx.z;
    const int b = z / 3;
    const int which = z - b * 3;
    const int t = threadIdx.x;

    const float* __restrict__ X = (which == 0) ? q : (which == 1) ? k : v;
    const float* __restrict__ W = (which == 0) ? Wq : (which == 1) ? Wk : Wv;
    u32* __restrict__ O = (which == 0) ? g_qp : (which == 1) ? g_kp : g_vp;

    for (int idx = t; idx < DK * DK; idx += 256) {
        int j = idx >> 5, i = idx & 31;
        wt[j * DK + i] = W[h * DK * DK + i * DK + j];
    }
    __syncthreads();

    const int l0 = blockIdx.x * 512 + t * 2;
    const float mv0 = mask[b * L + l0];
    const float mv1 = mask[b * L + l0 + 1];
    const int xbase = (b * D + h * DK) * L + l0;
    const int obase = (b * H + h) * DK * L + l0;

    u64 acc[2][16];
    #pragma unroll
    for (int p = 0; p < 2; p++)
        #pragma unroll
        for (int i = 0; i < 16; i++) acc[p][i] = 0ull;

    #pragma unroll
    for (int j = 0; j < DK; j++) {
        float2 xv = *(const float2*)&X[xbase + j * L];
        u64 x0 = f2dup(xv.x);
        u64 x1 = f2dup(xv.y);
        #pragma unroll
        for (int q4 = 0; q4 < 8; q4++) {
            float4 w4 = *(const float4*)&wt[j * DK + q4 * 4];
            u64 wp0 = f2pack(w4.x, w4.y);
            u64 wp1 = f2pack(w4.z, w4.w);
            fma2(acc[0][q4 * 2 + 0], x0, wp0);
            fma2(acc[0][q4 * 2 + 1], x0, wp1);
            fma2(acc[1][q4 * 2 + 0], x1, wp0);
            fma2(acc[1][q4 * 2 + 1], x1, wp1);
        }
    }

    #pragma unroll
    for (int ip = 0; ip < 16; ip++) {
        float2 r0 = f2unpack(acc[0][ip]);   // l0 : channels 2ip, 2ip+1
        float2 r1 = f2unpack(acc[1][ip]);   // l0+1
        uint2 s0, s1;
        s0.x = packsplit(r0.x * mv0); s0.y = packsplit(r1.x * mv1);
        s1.x = packsplit(r0.y * mv0); s1.y = packsplit(r1.y * mv1);
        *(uint2*)&O[obase + (2 * ip + 0) * L] = s0;
        *(uint2*)&O[obase + (2 * ip + 1) * L] = s1;
    }
}

// ---------------------------------------------------------------------------
// Kernel 2: fused attention, bf16x3 tensor-core (mma.sync m16n8k16).
// CTA: 128 rows x full L loop, 8 warps, warp tile = 16 rows x 64 cols.
// ---------------------------------------------------------------------------
#define QP 48      // Qs pitch (bf16): 96B rows, 16B aligned
#define KP 72      // Ks/Vs pitch: 144B rows
// dynamic smem byte offsets
#define SM_QSH 0
#define SM_QSL 12288
#define SM_KSH 24576
#define SM_KSL 29184
#define SM_VSH 33792
#define SM_VSL 38400
#define SM_MK  43008
#define SM_TOT 43264

__global__ __launch_bounds__(256) void attn_kernel(const float* __restrict__ mask)
{
    extern __shared__ char smb[];
    unsigned short* Qsh = (unsigned short*)(smb + SM_QSH);  // [m][c]
    unsigned short* Qsl = (unsigned short*)(smb + SM_QSL);
    unsigned short* Ksh = (unsigned short*)(smb + SM_KSH);  // [c][n]
    unsigned short* Ksl = (unsigned short*)(smb + SM_KSL);
    unsigned short* Vsh = (unsigned short*)(smb + SM_VSH);  // [d][n]
    unsigned short* Vsl = (unsigned short*)(smb + SM_VSL);
    float* mk = (float*)(smb + SM_MK);

    const int bh = blockIdx.y;
    const int b = bh / H;
    const int row0 = blockIdx.x * 128;

    const u32* __restrict__ qb = g_qp + bh * DK * L;
    const u32* __restrict__ kbp = g_kp + bh * DK * L;
    const u32* __restrict__ vbp = g_vp + bh * DK * L;
    const float* __restrict__ mp = mask + b * L;

    const int t = threadIdx.x;
    const int lane = t & 31;
    const int warp = t >> 5;
    const int R0 = warp * 16;
    const int qid = lane & 3;

    // ---- Q fill: [m][c] hi/lo planes, u32 stores of c-pairs ----
    #pragma unroll
    for (int i = 0; i < 8; i++) {
        int idx = i * 256 + t;
        int m = idx >> 4, cp = idx & 15;
        u32 q0 = qb[(2 * cp + 0) * L + row0 + m];
        u32 q1 = qb[(2 * cp + 1) * L + row0 + m];
        *(u32*)&Qsh[m * QP + 2 * cp] = ((q1 & 0xFFFFu) << 16) | (q0 & 0xFFFFu);
        *(u32*)&Qsl[m * QP + 2 * cp] = (q1 & 0xFFFF0000u) | (q0 >> 16);
    }

    // ---- prefetch K/V tile 0 (packed, coalesced uint2) ----
    uint2 kpre[4], vpre[4];
    #pragma unroll
    for (int i = 0; i < 4; i++) {
        int idx = i * 256 + t;
        int c = idx >> 5, np = idx & 31;
        kpre[i] = *(const uint2*)&kbp[c * L + 2 * np];
        vpre[i] = *(const uint2*)&vbp[c * L + 2 * np];
    }
    float mpre = (t < 64) ? mp[t] : 0.f;

    __syncthreads();   // Q planes visible

    // ---- Q fragments (persistent): A m16k16, kt = 0,1 ----
    u32 qah[2][4], qal[2][4];
    #pragma unroll
    for (int kt = 0; kt < 2; kt++) {
        int arow = R0 + (lane & 15);
        int acol = kt * 16 + (lane >> 4) * 8;
        ldsm4(qah[kt][0], qah[kt][1], qah[kt][2], qah[kt][3], smaddr(&Qsh[arow * QP + acol]));
        ldsm4(qal[kt][0], qal[kt][1], qal[kt][2], qal[kt][3], smaddr(&Qsl[arow * QP + acol]));
    }

    float oa[4][4];
    #pragma unroll
    for (int i = 0; i < 4; i++)
        #pragma unroll
        for (int j = 0; j < 4; j++) oa[i][j] = 0.f;
    float ps0 = 0.f, ps1 = 0.f;

    for (int col0 = 0; col0 < L; col0 += 64) {
        __syncthreads();   // prior tile's ldmatrix reads done

        #pragma unroll
        for (int i = 0; i < 4; i++) {
            int idx = i * 256 + t;
            int c = idx >> 5, np = idx & 31;
            *(u32*)&Ksh[c * KP + 2 * np] = ((kpre[i].y & 0xFFFFu) << 16) | (kpre[i].x & 0xFFFFu);
            *(u32*)&Ksl[c * KP + 2 * np] = (kpre[i].y & 0xFFFF0000u) | (kpre[i].x >> 16);
            *(u32*)&Vsh[c * KP + 2 * np] = ((vpre[i].y & 0xFFFFu) << 16) | (vpre[i].x & 0xFFFFu);
            *(u32*)&Vsl[c * KP + 2 * np] = (vpre[i].y & 0xFFFF0000u) | (vpre[i].x >> 16);
        }
        if (t < 64) mk[t] = mpre;
        __syncthreads();

        // prefetch next tile
        int nxt = col0 + 64;
        if (nxt < L) {
            #pragma unroll
            for (int i = 0; i < 4; i++) {
                int idx = i * 256 + t;
                int c = idx >> 5, np = idx & 31;
                kpre[i] = *(const uint2*)&kbp[c * L + nxt + 2 * np];
                vpre[i] = *(const uint2*)&vbp[c * L + nxt + 2 * np];
            }
            mpre = (t < 64) ? mp[nxt + t] : 0.f;
        }

        // ---- S = Q K^T : 8 n8-atoms, 3-pass bf16 ----
        float sa[8][4];
        #pragma unroll
        for (int i = 0; i < 8; i++)
            #pragma unroll
            for (int j = 0; j < 4; j++) sa[i][j] = 0.f;

        #pragma unroll
        for (int kt = 0; kt < 2; kt++) {
            int brow = kt * 16 + (lane & 15);
            #pragma unroll
            for (int nb = 0; nb < 4; nb++) {
                u32 addr_off = (u32)(brow * KP + nb * 16 + (lane >> 4) * 8);
                u32 bh0, bh1, bh2, bh3, bl0, bl1, bl2, bl3;
                ldsm4t(bh0, bh1, bh2, bh3, smaddr(&Ksh[addr_off]));
                ldsm4t(bl0, bl1, bl2, bl3, smaddr(&Ksl[addr_off]));
                mma16816(sa[2 * nb + 0], qah[kt], bh0, bh1);
                mma16816(sa[2 * nb + 0], qah[kt], bl0, bl1);
                mma16816(sa[2 * nb + 0], qal[kt], bh0, bh1);
                mma16816(sa[2 * nb + 1], qah[kt], bh2, bh3);
                mma16816(sa[2 * nb + 1], qah[kt], bl2, bl3);
                mma16816(sa[2 * nb + 1], qal[kt], bh2, bh3);
            }
        }

        // ---- P = mask * exp(S); row sums; build A-fragments (hi/lo) ----
        u32 pah[4][4], pal[4][4];
        #pragma unroll
        for (int nj = 0; nj < 8; nj++) {
            float2 mm = *(const float2*)&mk[8 * nj + 2 * qid];
            float p0 = mm.x * __expf(sa[nj][0]);
            float p1 = mm.y * __expf(sa[nj][1]);
            float p2 = mm.x * __expf(sa[nj][2]);
            float p3 = mm.y * __expf(sa[nj][3]);
            ps0 += p0 + p1;
            ps1 += p2 + p3;
            u32 h01 = cvtbf2(p1, p0);
            u32 h23 = cvtbf2(p3, p2);
            float hf0 = __uint_as_float(h01 << 16);
            float hf1 = __uint_as_float(h01 & 0xFFFF0000u);
            float hf2 = __uint_as_float(h23 << 16);
            float hf3 = __uint_as_float(h23 & 0xFFFF0000u);
            u32 l01 = cvtbf2(p1 - hf1, p0 - hf0);
            u32 l23 = cvtbf2(p3 - hf3, p2 - hf2);
            int ktp = nj >> 1, od = nj & 1;
            pah[ktp][od * 2 + 0] = h01;   // a0/a2: rows r,   k-lo/k-hi
            pah[ktp][od * 2 + 1] = h23;   // a1/a3: rows r+8
            pal[ktp][od * 2 + 0] = l01;
            pal[ktp][od * 2 + 1] = l23;
        }

        // ---- O += P V^T : 4 k16-steps x 2 d16-blocks, 3-pass ----
        #pragma unroll
        for (int ktp = 0; ktp < 4; ktp++) {
            #pragma unroll
            for (int db = 0; db < 2; db++) {
                u32 addr_off = (u32)((db * 16 + (lane & 15)) * KP + ktp * 16 + (lane >> 4) * 8);
                u32 vh0, vh1, vh2, vh3, vl0, vl1, vl2, vl3;
                ldsm4(vh0, vh1, vh2, vh3, smaddr(&Vsh[addr_off]));
                ldsm4(vl0, vl1, vl2, vl3, smaddr(&Vsl[addr_off]));
                mma16816(oa[2 * db + 0], pah[ktp], vh0, vh2);
                mma16816(oa[2 * db + 0], pah[ktp], vl0, vl2);
                mma16816(oa[2 * db + 0], pal[ktp], vh0, vh2);
                mma16816(oa[2 * db + 1], pah[ktp], vh1, vh3);
                mma16816(oa[2 * db + 1], pah[ktp], vl1, vl3);
                mma16816(oa[2 * db + 1], pal[ktp], vh1, vh3);
            }
        }
    }

    // ---- quad-reduce row sums (lanes of a quad share rows) ----
    ps0 += __shfl_xor_sync(0xFFFFFFFFu, ps0, 1);
    ps0 += __shfl_xor_sync(0xFFFFFFFFu, ps0, 2);
    ps1 += __shfl_xor_sync(0xFFFFFFFFu, ps1, 1);
    ps1 += __shfl_xor_sync(0xFFFFFFFFu, ps1, 2);
    const float inv0 = 1.0f / (ps0 + EPSV);
    const float inv1 = 1.0f / (ps1 + EPSV);

    // ---- store O to g_val[b][row][h*32 + col] ----
    const int h = bh - b * H;
    const int r = row0 + R0 + (lane >> 2);
    const int cbase = h * DK + 2 * qid;
    #pragma unroll
    for (int dj = 0; dj < 4; dj++) {
        *(float2*)&g_val[(size_t)(b * L + r) * D + cbase + 8 * dj] =
            make_float2(oa[dj][0] * inv0, oa[dj][1] * inv0);
        *(float2*)&g_val[(size_t)(b * L + r + 8) * D + cbase + 8 * dj] =
            make_float2(oa[dj][2] * inv1, oa[dj][3] * inv1);
    }
}

// ---------------------------------------------------------------------------
// Kernel 3: out = mask * (Wp @ val + bp), output layout (B, L, D)
// ---------------------------------------------------------------------------
#define OK_LD 68

__global__ __launch_bounds__(256) void out_kernel(
    const float* __restrict__ Wp, const float* __restrict__ bp,
    const float* __restrict__ mask, float* __restrict__ out)
{
    __shared__ __align__(16) float As[32 * OK_LD];   // [j][l]
    __shared__ __align__(16) float Bsm[32 * OK_LD];  // [j][i]

    const int b = blockIdx.z;
    const int i0 = blockIdx.y * 64;
    const int l0 = blockIdx.x * 64;
    const int t = threadIdx.x;
    const int rg = t >> 4, cg = t & 15;
    const int lr = rg * 4, ic = cg * 4;

    const float* __restrict__ val = g_val + b * L * D;

    int fl[8], fj[8];
    #pragma unroll
    for (int i = 0; i < 8; i++) {
        int idx = i * 256 + t;
        fl[i] = idx >> 5;
        fj[i] = idx & 31;
    }

    float ab[8], bb[8];
    #pragma unroll
    for (int i = 0; i < 8; i++) {
        ab[i] = val[(l0 + fl[i]) * D + fj[i]];
        bb[i] = Wp[(i0 + fl[i]) * D + fj[i]];
    }

    u64 acc2[2][4];
    #pragma unroll
    for (int p = 0; p < 2; p++)
        #pragma unroll
        for (int i = 0; i < 4; i++) acc2[p][i] = 0ull;

    for (int j0 = 0; j0 < D; j0 += 32) {
        __syncthreads();
        #pragma unroll
        for (int i = 0; i < 8; i++) {
            As[fj[i] * OK_LD + fl[i]] = ab[i];
            Bsm[fj[i] * OK_LD + fl[i]] = bb[i];
        }
        __syncthreads();

        int jn = j0 + 32;
        if (jn < D) {
            #pragma unroll
            for (int i = 0; i < 8; i++) {
                ab[i] = val[(l0 + fl[i]) * D + jn + fj[i]];
                bb[i] = Wp[(i0 + fl[i]) * D + jn + fj[i]];
            }
        }

        #pragma unroll
        for (int kk = 0; kk < 32; kk++) {
            float4 av = *(const float4*)&As[kk * OK_LD + lr];
            float4 bv = *(const float4*)&Bsm[kk * OK_LD + ic];
            u64 a01 = f2pack(av.x, av.y);
            u64 a23 = f2pack(av.z, av.w);
            u64 b0 = f2dup(bv.x), b1 = f2dup(bv.y), b2 = f2dup(bv.z), b3 = f2dup(bv.w);
            fma2(acc2[0][0], a01, b0); fma2(acc2[1][0], a23, b0);
            fma2(acc2[0][1], a01, b1); fma2(acc2[1][1], a23, b1);
            fma2(acc2[0][2], a01, b2); fma2(acc2[1][2], a23, b2);
            fma2(acc2[0][3], a01, b3); fma2(acc2[1][3], a23, b3);
        }
    }

    const float bv0 = bp[i0 + ic + 0];
    const float bv1 = bp[i0 + ic + 1];
    const float bv2 = bp[i0 + ic + 2];
    const float bv3 = bp[i0 + ic + 3];

    float2 c0r = f2unpack(acc2[0][0]), c1r = f2unpack(acc2[0][1]);
    float2 c2r = f2unpack(acc2[0][2]), c3r = f2unpack(acc2[0][3]);
    float2 d0r = f2unpack(acc2[1][0]), d1r = f2unpack(acc2[1][1]);
    float2 d2r = f2unpack(acc2[1][2]), d3r = f2unpack(acc2[1][3]);

    float rows[4][4] = {
        {c0r.x, c1r.x, c2r.x, c3r.x},
        {c0r.y, c1r.y, c2r.y, c3r.y},
        {d0r.x, d1r.x, d2r.x, d3r.x},
        {d0r.y, d1r.y, d2r.y, d3r.y},
    };

    #pragma unroll
    for (int p = 0; p < 4; p++) {
        float mv = mask[b * L + l0 + lr + p];
        float4 r;
        r.x = (rows[p][0] + bv0) * mv;
        r.y = (rows[p][1] + bv1) * mv;
        r.z = (rows[p][2] + bv2) * mv;
        r.w = (rows[p][3] + bv3) * mv;
        *(float4*)&out[((size_t)(b * L + l0 + lr + p)) * D + i0 + ic] = r;
    }
}

// ---------------------------------------------------------------------------
extern "C" void kernel_launch(void* const* d_in, const int* in_sizes, int n_in,
                              void* d_out, int out_size)
{
    const float* q    = (const float*)d_in[0];
    const float* k    = (const float*)d_in[1];
    const float* v    = (const float*)d_in[2];
    const float* mask = (const float*)d_in[3];
    const float* Wq   = (const float*)d_in[4];
    const float* Wk   = (const float*)d_in[5];
    const float* Wv   = (const float*)d_in[6];
    const float* Wp   = (const float*)d_in[7];
    const float* bp   = (const float*)d_in[8];
    float* out = (float*)d_out;

    cudaFuncSetAttribute(attn_kernel, cudaFuncAttributeMaxDynamicSharedMemorySize, SM_TOT);

    proj_kernel<<<dim3(L / 512, H, BS * 3), 256>>>(q, k, v, mask, Wq, Wk, Wv);
    attn_kernel<<<dim3(L / 128, BS * H), 256, SM_TOT>>>(mask);
    out_kernel<<<dim3(L / 64, D / 64, BS), 256>>>(Wp, bp, mask, out);
}